// round 1
// baseline (speedup 1.0000x reference)
#include <cuda_runtime.h>
#include <math.h>

#define N_  4
#define P_  2048
#define D_  512
#define H_  8
#define HD_ 64
#define QT  128          // q rows per block
#define KT  64           // k rows per tile
#define PAD 68           // smem row pad (floats): bank stride 4, float4-aligned
#define NTILES (P_/KT)   // 32
#define OUT_ELEMS   (N_*P_*D_)            // 4194304
#define ATTN_ELEMS  ((size_t)N_*H_*P_*P_) // 134217728

// ---------------- scratch (device globals: no allocation allowed) ----------
__device__ float g_q[N_*H_*P_*HD_];
__device__ float g_k[N_*H_*P_*HD_];
__device__ float g_v[N_*H_*P_*HD_];
__device__ float g_o[N_*P_*D_];
__device__ float g_mused[N_*H_*P_*NTILES];
__device__ float g_mfin[N_*H_*P_];
__device__ float g_lfin[N_*H_*P_];

// ======================= 1) QKV projection =================================
// q[n,h,p,e] = sum_d x[n,p,h*64+d] * Wq[e,d]   (layout (n,h,p,e) for attention)
// block: 512 threads, 8 points per block. Dynamic smem: W (padded) + x rows.
#define QKV_RPB 8
#define QKV_WS  (64*65)              // one weight matrix, padded rows
#define QKV_SMEM_FLOATS (3*QKV_WS + QKV_RPB*512)

__global__ __launch_bounds__(512) void qkv_kernel(
    const float* __restrict__ x, const float* __restrict__ Wq,
    const float* __restrict__ Wk, const float* __restrict__ Wv)
{
    extern __shared__ float sm[];
    float* ws = sm;                       // [3][64*65]
    float* xs = sm + 3*QKV_WS;            // [QKV_RPB][512]
    int t = threadIdx.x;
    for (int i = t; i < 64*64; i += 512) {
        int e = i >> 6, d = i & 63;
        ws[0*QKV_WS + e*65 + d] = Wq[i];
        ws[1*QKV_WS + e*65 + d] = Wk[i];
        ws[2*QKV_WS + e*65 + d] = Wv[i];
    }
    int p0 = blockIdx.x * QKV_RPB;
    #pragma unroll
    for (int r = 0; r < QKV_RPB; r++)
        xs[r*512 + t] = x[(size_t)(p0 + r)*D_ + t];
    __syncthreads();

    int h = t >> 6, e = t & 63;
    const float* wq = ws + 0*QKV_WS + e*65;
    const float* wk = ws + 1*QKV_WS + e*65;
    const float* wv = ws + 2*QKV_WS + e*65;
    for (int r = 0; r < QKV_RPB; r++) {
        const float* xh = xs + r*512 + h*HD_;
        float aq = 0.f, ak = 0.f, av = 0.f;
        #pragma unroll 16
        for (int d = 0; d < 64; d++) {
            float xv = xh[d];
            aq = fmaf(xv, wq[d], aq);
            ak = fmaf(xv, wk[d], ak);
            av = fmaf(xv, wv[d], av);
        }
        int np = p0 + r;
        int n = np >> 11, p = np & (P_-1);
        int idx = ((n*H_ + h)*P_ + p)*HD_ + e;
        g_q[idx] = aq; g_k[idx] = ak; g_v[idx] = av;
    }
}

// ======================= 2) attention (flash, deferred normalization) ======
// grid (P/QT, H, N), 256 threads. Each 16-lane group owns 8 q-rows.
// cols via c = lane16 + 16*j (bank-friendly). Writes unnormalized
// exp(s - m_tile) to attn buffer; fixup kernel normalizes later.
#define ATTN_SMEM_FLOATS ((QT + KT + KT + QT)*PAD)   // qs, ks, vs, as_

__global__ __launch_bounds__(256) void attn_kernel(
    float* __restrict__ attn, int store_attn)
{
    extern __shared__ float sm[];
    float* qs  = sm;                 // [QT][PAD]
    float* ks  = qs + QT*PAD;        // [KT][PAD]
    float* vs  = ks + KT*PAD;        // [KT][PAD]
    float* as_ = vs + KT*PAD;        // [QT][PAD]

    const int t   = threadIdx.x;
    const int qt  = blockIdx.x;
    const int h   = blockIdx.y;
    const int n   = blockIdx.z;
    const int nh  = n*H_ + h;
    const float scale = 0.044194173824159216f;   // 1/sqrt(512)

    const float* qbase = g_q + (size_t)nh*P_*HD_ + (size_t)qt*QT*HD_;
    const float* kbase = g_k + (size_t)nh*P_*HD_;
    const float* vbase = g_v + (size_t)nh*P_*HD_;
    float* abase = attn + (size_t)nh*P_*P_ + (size_t)qt*QT*P_;

    // load Q tile (scale folded in)
    for (int i = t*4; i < QT*HD_; i += 256*4) {
        int r = i >> 6, c = i & 63;
        float4 vq = *(const float4*)(qbase + i);
        vq.x *= scale; vq.y *= scale; vq.z *= scale; vq.w *= scale;
        *(float4*)(qs + r*PAD + c) = vq;
    }

    const int g   = t >> 4;       // 16 groups
    const int c16 = t & 15;       // lane within group
    const int qi0 = g * 8;        // 8 rows per group

    float m_run[8], l_run[8];
    #pragma unroll
    for (int i = 0; i < 8; i++) { m_run[i] = -1e30f; l_run[i] = 0.f; }
    float o_acc[8][4];
    #pragma unroll
    for (int i = 0; i < 8; i++)
        #pragma unroll
        for (int j = 0; j < 4; j++) o_acc[i][j] = 0.f;

    for (int kt_i = 0; kt_i < NTILES; kt_i++) {
        __syncthreads();     // all groups done reading previous ks/vs
        const float* kp = kbase + kt_i*KT*HD_;
        const float* vp = vbase + kt_i*KT*HD_;
        for (int i = t*4; i < KT*HD_; i += 256*4) {
            int r = i >> 6, c = i & 63;
            *(float4*)(ks + r*PAD + c) = *(const float4*)(kp + i);
            *(float4*)(vs + r*PAD + c) = *(const float4*)(vp + i);
        }
        __syncthreads();

        // ---- S = Q K^T (rows qi0..qi0+7, cols c16+16j) ----
        float acc[8][4];
        #pragma unroll
        for (int i = 0; i < 8; i++)
            #pragma unroll
            for (int j = 0; j < 4; j++) acc[i][j] = 0.f;

        #pragma unroll 8
        for (int d4 = 0; d4 < 16; d4++) {
            float4 kv4[4];
            #pragma unroll
            for (int j = 0; j < 4; j++)
                kv4[j] = *(float4*)(ks + (c16 + 16*j)*PAD + d4*4);
            #pragma unroll
            for (int i = 0; i < 8; i++) {
                float4 q4 = *(float4*)(qs + (qi0 + i)*PAD + d4*4);
                #pragma unroll
                for (int j = 0; j < 4; j++) {
                    acc[i][j] = fmaf(q4.x, kv4[j].x, acc[i][j]);
                    acc[i][j] = fmaf(q4.y, kv4[j].y, acc[i][j]);
                    acc[i][j] = fmaf(q4.z, kv4[j].z, acc[i][j]);
                    acc[i][j] = fmaf(q4.w, kv4[j].w, acc[i][j]);
                }
            }
        }

        // ---- online softmax per row (in-register state, shfl reductions) ----
        #pragma unroll
        for (int i = 0; i < 8; i++) {
            float tmax = fmaxf(fmaxf(acc[i][0], acc[i][1]),
                               fmaxf(acc[i][2], acc[i][3]));
            #pragma unroll
            for (int w = 1; w < 16; w <<= 1)
                tmax = fmaxf(tmax, __shfl_xor_sync(0xffffffffu, tmax, w));
            float m_new = fmaxf(m_run[i], tmax);

            float p0 = __expf(acc[i][0] - m_new);
            float p1 = __expf(acc[i][1] - m_new);
            float p2 = __expf(acc[i][2] - m_new);
            float p3 = __expf(acc[i][3] - m_new);
            float psum = (p0 + p1) + (p2 + p3);
            #pragma unroll
            for (int w = 1; w < 16; w <<= 1)
                psum += __shfl_xor_sync(0xffffffffu, psum, w);

            float resc = __expf(m_run[i] - m_new);
            l_run[i] = l_run[i] * resc + psum;
            m_run[i] = m_new;
            #pragma unroll
            for (int j = 0; j < 4; j++) o_acc[i][j] *= resc;

            // stash p: smem for AV phase + gmem (unnormalized)
            float* ar = as_ + (qi0 + i)*PAD;
            ar[c16 +  0] = p0; ar[c16 + 16] = p1;
            ar[c16 + 32] = p2; ar[c16 + 48] = p3;
            if (store_attn) {
                float* gr = abase + (size_t)(qi0 + i)*P_ + kt_i*KT;
                gr[c16 +  0] = p0; gr[c16 + 16] = p1;
                gr[c16 + 32] = p2; gr[c16 + 48] = p3;
            }
            if (c16 == 0)
                g_mused[((size_t)nh*P_ + qt*QT + qi0 + i)*NTILES + kt_i] = m_new;
        }
        __syncwarp();

        // ---- O += P * V  (same rows, cols e = c16+16j) ----
        #pragma unroll 4
        for (int kk4 = 0; kk4 < 16; kk4++) {
            float4 a4[8];
            #pragma unroll
            for (int i = 0; i < 8; i++)
                a4[i] = *(float4*)(as_ + (qi0 + i)*PAD + kk4*4);
            #pragma unroll
            for (int u = 0; u < 4; u++) {
                float vv[4];
                #pragma unroll
                for (int j = 0; j < 4; j++)
                    vv[j] = vs[(kk4*4 + u)*PAD + c16 + 16*j];
                #pragma unroll
                for (int i = 0; i < 8; i++) {
                    float a = (u == 0) ? a4[i].x : (u == 1) ? a4[i].y
                            : (u == 2) ? a4[i].z : a4[i].w;
                    #pragma unroll
                    for (int j = 0; j < 4; j++)
                        o_acc[i][j] = fmaf(a, vv[j], o_acc[i][j]);
                }
            }
        }
        __syncwarp();
    }

    // ---- epilogue: normalize o, write scratch; record m_fin/l_fin ----
    #pragma unroll
    for (int i = 0; i < 8; i++) {
        float inv_l = 1.f / l_run[i];
        int prow = qt*QT + qi0 + i;                  // point index within (n)
        float* orow = g_o + ((size_t)n*P_ + prow)*D_ + h*HD_;
        #pragma unroll
        for (int j = 0; j < 4; j++)
            orow[c16 + 16*j] = o_acc[i][j] * inv_l;
        if (c16 == 0) {
            g_mfin[(size_t)nh*P_ + prow] = m_run[i];
            g_lfin[(size_t)nh*P_ + prow] = l_run[i];
        }
    }
}

// ======================= 3) attention normalization fixup ==================
__global__ __launch_bounds__(256) void fixup_kernel(float* __restrict__ attn)
{
    size_t idx = ((size_t)blockIdx.x * 256 + threadIdx.x) * 4;
    size_t row  = idx >> 11;            // / P_
    int    col  = (int)(idx & (P_ - 1));
    int    tile = col >> 6;             // / KT
    float m_u = g_mused[row*NTILES + tile];
    float f   = __expf(m_u - g_mfin[row]) / g_lfin[row];
    float4 a = *(float4*)(attn + idx);
    a.x *= f; a.y *= f; a.z *= f; a.w *= f;
    *(float4*)(attn + idx) = a;
}

// ======================= 4) output projection ==============================
// out[r][c] = sum_d g_o[r][d] * Wo[c][d] + bo[c]
#define OP_PAD 36
__global__ __launch_bounds__(256) void proj_kernel(
    const float* __restrict__ Wo, const float* __restrict__ bo,
    float* __restrict__ out)
{
    __shared__ float As[128*OP_PAD];
    __shared__ float Ws[64*OP_PAD];
    const int t = threadIdx.x;
    const int rb = blockIdx.x * 128, cb = blockIdx.y * 64;
    const int g = t >> 4, c16 = t & 15;
    const int r0 = g * 8;
    float acc[8][4];
    #pragma unroll
    for (int i = 0; i < 8; i++)
        #pragma unroll
        for (int j = 0; j < 4; j++) acc[i][j] = 0.f;

    for (int dc = 0; dc < 512; dc += 32) {
        __syncthreads();
        for (int i = t*4; i < 128*32; i += 256*4) {
            int r = i >> 5, c = i & 31;
            *(float4*)(As + r*OP_PAD + c) =
                *(const float4*)(g_o + (size_t)(rb + r)*512 + dc + c);
        }
        for (int i = t*4; i < 64*32; i += 256*4) {
            int r = i >> 5, c = i & 31;
            *(float4*)(Ws + r*OP_PAD + c) =
                *(const float4*)(Wo + (size_t)(cb + r)*512 + dc + c);
        }
        __syncthreads();
        #pragma unroll
        for (int d4 = 0; d4 < 8; d4++) {
            float4 w4[4];
            #pragma unroll
            for (int j = 0; j < 4; j++)
                w4[j] = *(float4*)(Ws + (c16 + 16*j)*OP_PAD + d4*4);
            #pragma unroll
            for (int i = 0; i < 8; i++) {
                float4 a4 = *(float4*)(As + (r0 + i)*OP_PAD + d4*4);
                #pragma unroll
                for (int j = 0; j < 4; j++) {
                    acc[i][j] = fmaf(a4.x, w4[j].x, acc[i][j]);
                    acc[i][j] = fmaf(a4.y, w4[j].y, acc[i][j]);
                    acc[i][j] = fmaf(a4.z, w4[j].z, acc[i][j]);
                    acc[i][j] = fmaf(a4.w, w4[j].w, acc[i][j]);
                }
            }
        }
    }
    #pragma unroll
    for (int j = 0; j < 4; j++) {
        float b = bo[cb + c16 + 16*j];
        #pragma unroll
        for (int i = 0; i < 8; i++)
            out[(size_t)(rb + r0 + i)*512 + cb + c16 + 16*j] = acc[i][j] + b;
    }
}

// ======================= launch ============================================
extern "C" void kernel_launch(void* const* d_in, const int* in_sizes, int n_in,
                              void* d_out, int out_size)
{
    const float* xyz = (const float*)d_in[0];
    const float* Wq  = (const float*)d_in[1];
    const float* Wk  = (const float*)d_in[2];
    const float* Wv  = (const float*)d_in[3];
    const float* Wo  = (const float*)d_in[4];
    const float* bo  = (const float*)d_in[5];
    float* out = (float*)d_out;

    // output assumed concatenated in return order: out (4,2048,512), attention (4,8,2048,2048)
    int store_attn = (out_size >= (int)(OUT_ELEMS + ATTN_ELEMS)) ? 1 : 0;
    float* attn = store_attn ? (out + OUT_ELEMS) : out;  // unused when !store_attn

    cudaFuncSetAttribute(qkv_kernel, cudaFuncAttributeMaxDynamicSharedMemorySize,
                         QKV_SMEM_FLOATS * 4);
    cudaFuncSetAttribute(attn_kernel, cudaFuncAttributeMaxDynamicSharedMemorySize,
                         ATTN_SMEM_FLOATS * 4);

    qkv_kernel<<<(N_*P_)/QKV_RPB, 512, QKV_SMEM_FLOATS*4>>>(xyz, Wq, Wk, Wv);
    attn_kernel<<<dim3(P_/QT, H_, N_), 256, ATTN_SMEM_FLOATS*4>>>(attn, store_attn);
    if (store_attn)
        fixup_kernel<<<(unsigned)(ATTN_ELEMS/4/256), 256>>>(attn);
    proj_kernel<<<dim3((N_*P_)/128, D_/64), 256>>>(Wo, bo, out);
}